// round 4
// baseline (speedup 1.0000x reference)
#include <cuda_runtime.h>
#include <math.h>

#define NN 100000
#define NE 1600000
#define KTOT 164          // padded K (real 161)
#define KC 41             // K-chunk: 4 chunks exactly
#define AS_STRIDE 132
#define WS_STRIDE 132

// ---------------- scratch (device globals: allocation-free) ----------------
__device__ __align__(16) float g_zf[NN * 64];    // x_in @ W_filt[:64,:]
__device__ __align__(16) float g_zb[NN * 64];    // x_in @ W_filt[64:,:]
__device__ __align__(16) float g_acc[NN * 64];   // diffused accumulator
__device__ float g_degf[NN];
__device__ float g_degb[NN];
__device__ __align__(16) float g_Wk[KTOT * 128]; // folded weights, k-major [k][c]
__device__ __align__(16) float g_bz[128];        // folded bias
__device__ __align__(16) int4  g_erec[NE];       // (s, t, bits(wf), bits(wb))

// ---------------- init accumulator + degrees ----------------
__global__ void k_init() {
    int i = blockIdx.x * blockDim.x + threadIdx.x;
    int st = gridDim.x * blockDim.x;
    float4 z = make_float4(0.f, 0.f, 0.f, 0.f);
    for (int j = i; j < NN * 16; j += st)
        reinterpret_cast<float4*>(g_acc)[j] = z;
    for (int j = i; j < NN; j += st) { g_degf[j] = 0.f; g_degb[j] = 0.f; }
}

// ---------------- fold W_filt into W_in (k-major output) ----------------
__global__ void k_wfold(const float* __restrict__ Win, const float* __restrict__ bin,
                        const float* __restrict__ Wf) {
    __shared__ float wsel[64];
    int c = blockIdx.x;                 // 0..127
    if (threadIdx.x < 64) {
        int j = threadIdx.x;
        wsel[j] = (c < 64) ? Wf[j * 64 + c] : Wf[(64 + j) * 64 + (c - 64)];
    }
    __syncthreads();
    int k = threadIdx.x;
    if (k < KTOT) {
        float a = 0.f;
        if (k < 161) {
#pragma unroll 8
            for (int j = 0; j < 64; j++) a += Win[k * 64 + j] * wsel[j];
        }
        g_Wk[k * 128 + c] = a;
    }
    if (threadIdx.x == 0) {
        float b = 0.f;
        for (int j = 0; j < 64; j++) b += bin[j] * wsel[j];
        g_bz[c] = b;
    }
}

// ---------------- weighted degrees ----------------
__global__ void k_deg(const int* __restrict__ ei, const float* __restrict__ ew) {
    int e = blockIdx.x * blockDim.x + threadIdx.x;
    if (e >= NE) return;
    int s = ei[e], t = ei[NE + e];
    float w = ew[e];
    if (s != t) {
        atomicAdd(&g_degf[t], w);
        atomicAdd(&g_degb[s], w);
    }
}

// ---------------- per-edge record: (s, t, wf, wb) ----------------
__global__ void k_prep(const int* __restrict__ ei, const float* __restrict__ ew) {
    int e = blockIdx.x * blockDim.x + threadIdx.x;
    if (e >= NE) return;
    int s = ei[e], t = ei[NE + e];
    float w = (s == t) ? 0.f : ew[e];
    float df = __ldg(&g_degf[t]);
    float db = __ldg(&g_degb[s]);
    float wf = (df > 0.f) ? w / df : 0.f;
    float wb = (db > 0.f) ? w / db : 0.f;
    g_erec[e] = make_int4(s, t, __float_as_int(wf), __float_as_int(wb));
}

// ---------------- z = A @ Wc + bz  (SGEMM: 128x128 tile, 8x8 micro) ----------------
// A[m][k] = concat(x, x_hat_1, h)[m][k] generated on the fly.
__device__ __forceinline__ float a_elem(int m, int k,
                                        const float* __restrict__ x,
                                        const float* __restrict__ xh,
                                        const float* __restrict__ hh) {
    if (m >= NN || k >= 161) return 0.f;
    if (k == 0)  return x[m];
    if (k < 97)  return xh[(size_t)m * 96 + (k - 1)];
    return hh[(size_t)m * 64 + (k - 97)];
}

__global__ __launch_bounds__(256) void k_z(const float* __restrict__ x,
                                           const float* __restrict__ xh,
                                           const float* __restrict__ hh) {
    __shared__ float As[KC * AS_STRIDE];   // [kk][m]
    __shared__ float Ws[KC * WS_STRIDE];   // [kk][c]

    const int tid = threadIdx.x;
    const int tx = tid & 15;               // col group: cols tx*8 .. tx*8+7
    const int ty = tid >> 4;               // row group: rows ty*8 .. ty*8+7
    const int base = blockIdx.x * 128;

    float acc[8][8];
#pragma unroll
    for (int r = 0; r < 8; r++)
#pragma unroll
        for (int c = 0; c < 8; c++) acc[r][c] = 0.f;

    const float4 bb0 = *reinterpret_cast<const float4*>(&g_bz[tx * 8]);
    const float4 bb1 = *reinterpret_cast<const float4*>(&g_bz[tx * 8 + 4]);

    for (int ch = 0; ch < 4; ch++) {
        const int k0 = ch * KC;
        // load W chunk: [KC][128] -> Ws[kk][c] (coalesced float4)
        for (int i = tid; i < KC * 32; i += 256) {
            int kk = i >> 5, c4 = (i & 31) << 2;
            *reinterpret_cast<float4*>(&Ws[kk * WS_STRIDE + c4]) =
                *reinterpret_cast<const float4*>(&g_Wk[(k0 + kk) * 128 + c4]);
        }
        // load A chunk: rows base..base+127, k = k0..k0+KC-1 (k-contiguous reads)
        for (int i = tid; i < 128 * KC; i += 256) {
            int m = i / KC;
            int kk = i - m * KC;
            As[kk * AS_STRIDE + m] = a_elem(base + m, k0 + kk, x, xh, hh);
        }
        __syncthreads();

#pragma unroll 1
        for (int kk = 0; kk < KC; kk++) {
            float4 a0 = *reinterpret_cast<const float4*>(&As[kk * AS_STRIDE + ty * 8]);
            float4 a1 = *reinterpret_cast<const float4*>(&As[kk * AS_STRIDE + ty * 8 + 4]);
            float4 b0 = *reinterpret_cast<const float4*>(&Ws[kk * WS_STRIDE + tx * 8]);
            float4 b1 = *reinterpret_cast<const float4*>(&Ws[kk * WS_STRIDE + tx * 8 + 4]);
            float av[8] = {a0.x, a0.y, a0.z, a0.w, a1.x, a1.y, a1.z, a1.w};
            float bv[8] = {b0.x, b0.y, b0.z, b0.w, b1.x, b1.y, b1.z, b1.w};
#pragma unroll
            for (int r = 0; r < 8; r++)
#pragma unroll
                for (int c = 0; c < 8; c++) acc[r][c] += av[r] * bv[c];
        }
        __syncthreads();
    }

    // epilogue: add bias, write zf (cols<64) / zb (cols>=64)
    float* dst = (tx < 8) ? g_zf : g_zb;
    const int cdst = (tx < 8) ? tx * 8 : tx * 8 - 64;
#pragma unroll
    for (int r = 0; r < 8; r++) {
        int m = base + ty * 8 + r;
        if (m >= NN) break;
        float4 o0 = make_float4(acc[r][0] + bb0.x, acc[r][1] + bb0.y,
                                acc[r][2] + bb0.z, acc[r][3] + bb0.w);
        float4 o1 = make_float4(acc[r][4] + bb1.x, acc[r][5] + bb1.y,
                                acc[r][6] + bb1.z, acc[r][7] + bb1.w);
        *reinterpret_cast<float4*>(&dst[(size_t)m * 64 + cdst])     = o0;
        *reinterpret_cast<float4*>(&dst[(size_t)m * 64 + cdst + 4]) = o1;
    }
}

// ---------------- scatter: acc[t] += wf*zf[s]; acc[s] += wb*zb[t] ----------------
__device__ __forceinline__ void red4(float* p, float a, float b, float c, float d) {
    asm volatile("red.global.add.v4.f32 [%0], {%1, %2, %3, %4};"
                 :: "l"(p), "f"(a), "f"(b), "f"(c), "f"(d) : "memory");
}

__global__ __launch_bounds__(256) void k_scatter() {
    unsigned tid = blockIdx.x * 256u + threadIdx.x;
    unsigned e = tid >> 4;               // 16 lanes per edge
    if (e >= NE) return;
    int sub = threadIdx.x & 15;

    int4 rec = __ldg(&g_erec[e]);
    int s = rec.x, t = rec.y;
    float wf = __int_as_float(rec.z);
    float wb = __int_as_float(rec.w);

    float4 vs = *reinterpret_cast<const float4*>(g_zf + (size_t)s * 64 + 4 * sub);
    red4(g_acc + (size_t)t * 64 + 4 * sub, wf * vs.x, wf * vs.y, wf * vs.z, wf * vs.w);
    float4 vt = *reinterpret_cast<const float4*>(g_zb + (size_t)t * 64 + 4 * sub);
    red4(g_acc + (size_t)s * 64 + 4 * sub, wb * vt.x, wb * vt.y, wb * vt.z, wb * vt.w);
}

// ---------------- fused GMM heads + outputs ----------------
#define JP 132
#define HEAD_SMEM ((3 * 32 * JP + 160 + 8 * 4 * 128) * 4)

__global__ __launch_bounds__(256) void k_head(const float* __restrict__ hh,
                                              const float* __restrict__ bf,
                                              const float* __restrict__ Wm,  const float* __restrict__ bm,
                                              const float* __restrict__ Wsg, const float* __restrict__ bsg,
                                              const float* __restrict__ Wp,  const float* __restrict__ bp,
                                              float* __restrict__ out, int write_extra) {
    extern __shared__ float sm[];
    float* Wmt = sm;                    // [32][JP]
    float* Wst = Wmt + 32 * JP;
    float* Wpt = Wst + 32 * JP;
    float* bfs = Wpt + 32 * JP;         // 64
    float* bms = bfs + 64;              // 32
    float* bss = bms + 32;              // 32
    float* bps = bss + 32;              // 32
    float* cat = bps + 32;              // [8 warps][4 nodes][128]

    for (int i = threadIdx.x; i < 32 * JP; i += 256) { Wmt[i] = 0.f; Wst[i] = 0.f; Wpt[i] = 0.f; }
    __syncthreads();
    for (int i = threadIdx.x; i < 128 * 32; i += 256) {
        int j = i >> 5, c = i & 31;
        Wmt[c * JP + j] = Wm[i];
        Wst[c * JP + j] = Wsg[i];
        Wpt[c * JP + j] = Wp[i];
    }
    if (threadIdx.x < 64) bfs[threadIdx.x] = bf[threadIdx.x];
    if (threadIdx.x < 32) {
        bms[threadIdx.x] = bm[threadIdx.x];
        bss[threadIdx.x] = bsg[threadIdx.x];
        bps[threadIdx.x] = bp[threadIdx.x];
    }
    __syncthreads();

    const int lane = threadIdx.x & 31;
    const int wrp  = threadIdx.x >> 5;
    float* mycat = cat + wrp * 4 * 128;

    float* ogmm = out;
    float* oo1  = out + (size_t)NN * 96;
    float* oh   = out + (size_t)NN * 96 + (size_t)NN * 128;

    int base = blockIdx.x * 32 + wrp * 4;          // 3125 * 32 = NN exactly

    float a0[4], a1[4], h0[4], h1[4];
#pragma unroll
    for (int s = 0; s < 4; s++) {
        size_t n = (size_t)(base + s);
        a0[s] = g_acc[n * 64 + lane]      + bfs[lane];
        a1[s] = g_acc[n * 64 + 32 + lane] + bfs[lane + 32];
        h0[s] = hh[n * 64 + lane];
        h1[s] = hh[n * 64 + 32 + lane];
        float* c = mycat + s * 128;
        c[lane]      = a0[s];
        c[lane + 32] = a1[s];
        c[lane + 64] = h0[s];
        c[lane + 96] = h1[s];
    }
    __syncwarp();

    float am[4] = {0.f, 0.f, 0.f, 0.f};
    float as_[4] = {0.f, 0.f, 0.f, 0.f};
    float ap[4] = {0.f, 0.f, 0.f, 0.f};
    {
        const float4* wmp = reinterpret_cast<const float4*>(Wmt + lane * JP);
        const float4* wsp = reinterpret_cast<const float4*>(Wst + lane * JP);
        const float4* wpp = reinterpret_cast<const float4*>(Wpt + lane * JP);
#pragma unroll 8
        for (int j4 = 0; j4 < 32; j4++) {
            float4 wm = wmp[j4], ws = wsp[j4], wq = wpp[j4];
#pragma unroll
            for (int s = 0; s < 4; s++) {
                float4 v = reinterpret_cast<const float4*>(mycat + s * 128)[j4];
                am[s]  += wm.x * v.x + wm.y * v.y + wm.z * v.z + wm.w * v.w;
                as_[s] += ws.x * v.x + ws.y * v.y + ws.z * v.z + ws.w * v.w;
                ap[s]  += wq.x * v.x + wq.y * v.y + wq.z * v.z + wq.w * v.w;
            }
        }
    }

#pragma unroll
    for (int s = 0; s < 4; s++) {
        size_t n = (size_t)(base + s);
        float mu = am[s] + bms[lane];
        float sg = as_[s] + bss[lane];
        sg = fmaxf(sg, 0.f) + log1pf(__expf(-fabsf(sg)));   // stable softplus
        float pv = ap[s] + bps[lane];
        float m = pv;
#pragma unroll
        for (int o = 16; o; o >>= 1) m = fmaxf(m, __shfl_xor_sync(0xFFFFFFFFu, m, o));
        float ex = __expf(pv - m);
        float ssum = ex;
#pragma unroll
        for (int o = 16; o; o >>= 1) ssum += __shfl_xor_sync(0xFFFFFFFFu, ssum, o);
        float pi = ex / ssum;

        ogmm[n * 96 + lane]      = mu;
        ogmm[n * 96 + 32 + lane] = sg;
        ogmm[n * 96 + 64 + lane] = pi;
        if (write_extra) {
            oo1[n * 128 + lane]      = a0[s];
            oo1[n * 128 + 32 + lane] = a1[s];
            oo1[n * 128 + 64 + lane] = h0[s];
            oo1[n * 128 + 96 + lane] = h1[s];
            oh[n * 64 + lane]      = h0[s];
            oh[n * 64 + 32 + lane] = h1[s];
        }
    }
}

// ---------------- launch ----------------
extern "C" void kernel_launch(void* const* d_in, const int* in_sizes, int n_in,
                              void* d_out, int out_size) {
    const float* x   = (const float*)d_in[0];
    const float* xh  = (const float*)d_in[1];
    const float* h   = (const float*)d_in[2];
    const int*   ei  = (const int*)d_in[3];
    const float* ew  = (const float*)d_in[4];
    const float* Win = (const float*)d_in[5];
    const float* bin = (const float*)d_in[6];
    const float* Wf  = (const float*)d_in[7];
    const float* bf  = (const float*)d_in[8];
    const float* Wm  = (const float*)d_in[9];
    const float* bm  = (const float*)d_in[10];
    const float* Wsg = (const float*)d_in[11];
    const float* bsg = (const float*)d_in[12];
    const float* Wp  = (const float*)d_in[13];
    const float* bp  = (const float*)d_in[14];
    float* out = (float*)d_out;

    int write_extra = (out_size >= NN * 96 + NN * 128 + NN * 64) ? 1 : 0;

    cudaFuncSetAttribute(k_head, cudaFuncAttributeMaxDynamicSharedMemorySize, HEAD_SMEM);

    k_init<<<148, 256>>>();
    k_wfold<<<128, 192>>>(Win, bin, Wf);
    k_deg<<<(NE + 255) / 256, 256>>>(ei, ew);
    k_prep<<<(NE + 255) / 256, 256>>>(ei, ew);
    k_z<<<(NN + 127) / 128, 256>>>(x, xh, h);
    k_scatter<<<(NE * 16) / 256, 256>>>();
    k_head<<<3125, 256, HEAD_SMEM>>>(h, bf, Wm, bm, Wsg, bsg, Wp, bp, out, write_extra);
}

// round 6
// speedup vs baseline: 1.4254x; 1.4254x over previous
#include <cuda_runtime.h>
#include <math.h>
#include <stdint.h>

#define NN 100000
#define NE 1600000
#define KTOT 168          // K padded 161 -> 168 (21 k-steps of 8)
#define KPAD 172          // smem row stride (conflict-free)

// ---------------- scratch (device globals: allocation-free) ----------------
__device__ __align__(16) float g_zf[NN * 64];    // x_in @ W_filt[:64,:]
__device__ __align__(16) float g_zb[NN * 64];    // x_in @ W_filt[64:,:]
__device__ __align__(16) float g_acc[NN * 64];   // diffused accumulator
__device__ float g_degf[NN];
__device__ float g_degb[NN];
__device__ __align__(16) float g_Wk[KTOT * 128]; // folded weights (tf32-rounded), [k][c]
__device__ __align__(16) float g_bz[128];        // folded bias (fp32)

// ---------------- helpers ----------------
__device__ __forceinline__ unsigned f2tf32(float v) {
    unsigned o; asm("cvt.rna.tf32.f32 %0, %1;" : "=r"(o) : "f"(v)); return o;
}

__device__ __forceinline__ void mma_tf32(float* d,
                                         unsigned a0, unsigned a1, unsigned a2, unsigned a3,
                                         unsigned b0, unsigned b1) {
    asm volatile("mma.sync.aligned.m16n8k8.row.col.f32.tf32.tf32.f32 "
                 "{%0,%1,%2,%3}, {%4,%5,%6,%7}, {%8,%9}, {%0,%1,%2,%3};"
                 : "+f"(d[0]), "+f"(d[1]), "+f"(d[2]), "+f"(d[3])
                 : "r"(a0), "r"(a1), "r"(a2), "r"(a3), "r"(b0), "r"(b1));
}

// ---------------- init accumulator + degrees ----------------
__global__ void k_init() {
    int i = blockIdx.x * blockDim.x + threadIdx.x;
    int st = gridDim.x * blockDim.x;
    float4 z = make_float4(0.f, 0.f, 0.f, 0.f);
    for (int j = i; j < NN * 16; j += st)
        reinterpret_cast<float4*>(g_acc)[j] = z;
    for (int j = i; j < NN; j += st) { g_degf[j] = 0.f; g_degb[j] = 0.f; }
}

// ---------------- fold W_filt into W_in (k-major, tf32-rounded) ----------------
__global__ void k_wfold(const float* __restrict__ Win, const float* __restrict__ bin,
                        const float* __restrict__ Wf) {
    __shared__ float wsel[64];
    int c = blockIdx.x;                 // 0..127
    if (threadIdx.x < 64) {
        int j = threadIdx.x;
        wsel[j] = (c < 64) ? Wf[j * 64 + c] : Wf[(64 + j) * 64 + (c - 64)];
    }
    __syncthreads();
    int k = threadIdx.x;
    if (k < KTOT) {
        float a = 0.f;
        if (k < 161) {
#pragma unroll 8
            for (int j = 0; j < 64; j++) a += Win[k * 64 + j] * wsel[j];
        }
        g_Wk[k * 128 + c] = __uint_as_float(f2tf32(a));
    }
    if (threadIdx.x == 0) {
        float b = 0.f;
        for (int j = 0; j < 64; j++) b += bin[j] * wsel[j];
        g_bz[c] = b;
    }
}

// ---------------- weighted degrees ----------------
__global__ void k_deg(const int* __restrict__ ei, const float* __restrict__ ew) {
    int e = blockIdx.x * blockDim.x + threadIdx.x;
    if (e >= NE) return;
    int s = ei[e], t = ei[NE + e];
    float w = ew[e];
    if (s != t) {
        atomicAdd(&g_degf[t], w);
        atomicAdd(&g_degb[s], w);
    }
}

// ---------------- z = A @ Wc + bz  (tf32 tensor-core GEMM) ----------------
// Block: 128 rows x 128 cols, full K resident. 8 warps in 2(m) x 4(n) grid,
// each warp 64x32 via m16n8k8 fragments.
#define Z_SMEM (128 * KPAD * 4)

__global__ __launch_bounds__(256) void k_z(const float* __restrict__ x,
                                           const float* __restrict__ xh,
                                           const float* __restrict__ hh) {
    extern __shared__ float As[];       // [128][KPAD] tf32-rounded
    const int tid = threadIdx.x;
    const int base = blockIdx.x * 128;

    // zero-fill (covers k-pad and m >= NN rows)
    for (int i = tid; i < 128 * KPAD / 4; i += 256)
        reinterpret_cast<float4*>(As)[i] = make_float4(0.f, 0.f, 0.f, 0.f);
    __syncthreads();

    // stage A: three contiguous regions, tf32-convert on store
    {
        int lim = min(128, NN - base);
        if (tid < lim) As[tid * KPAD] = __uint_as_float(f2tf32(x[base + tid]));
        for (int i = tid; i < lim * 96; i += 256) {
            int m = i / 96, k = i - m * 96;
            As[m * KPAD + 1 + k] = __uint_as_float(f2tf32(xh[(size_t)(base + m) * 96 + k]));
        }
        for (int i = tid; i < lim * 64; i += 256) {
            int m = i >> 6, k = i & 63;
            As[m * KPAD + 97 + k] = __uint_as_float(f2tf32(hh[(size_t)(base + m) * 64 + k]));
        }
    }
    __syncthreads();

    const int lane = tid & 31;
    const int w    = tid >> 5;
    const int wm = (w >> 2) * 64;       // 0 | 64
    const int wn = (w & 3) * 32;        // 0,32,64,96
    const int g = lane >> 2, t = lane & 3;
    const unsigned* Au = reinterpret_cast<const unsigned*>(As);

    float acc[4][4][4];
#pragma unroll
    for (int mf = 0; mf < 4; mf++)
#pragma unroll
        for (int nf = 0; nf < 4; nf++)
#pragma unroll
            for (int q = 0; q < 4; q++) acc[mf][nf][q] = 0.f;

#pragma unroll 1
    for (int ks = 0; ks < 21; ks++) {
        const int k0 = ks * 8;
        unsigned bfr[4][2];
#pragma unroll
        for (int nf = 0; nf < 4; nf++) {
            int nc = wn + nf * 8 + g;
            bfr[nf][0] = __float_as_uint(__ldg(&g_Wk[(k0 + t) * 128 + nc]));
            bfr[nf][1] = __float_as_uint(__ldg(&g_Wk[(k0 + 4 + t) * 128 + nc]));
        }
#pragma unroll
        for (int mf = 0; mf < 4; mf++) {
            int r0 = wm + mf * 16 + g;
            unsigned a0 = Au[r0 * KPAD + k0 + t];
            unsigned a1 = Au[(r0 + 8) * KPAD + k0 + t];
            unsigned a2 = Au[r0 * KPAD + k0 + 4 + t];
            unsigned a3 = Au[(r0 + 8) * KPAD + k0 + 4 + t];
#pragma unroll
            for (int nf = 0; nf < 4; nf++)
                mma_tf32(acc[mf][nf], a0, a1, a2, a3, bfr[nf][0], bfr[nf][1]);
        }
    }

    // epilogue: add bias, route cols<64 -> zf, cols>=64 -> zb (col-64)
#pragma unroll
    for (int nf = 0; nf < 4; nf++) {
        int c = wn + nf * 8 + 2 * t;
        float bi0 = g_bz[c], bi1 = g_bz[c + 1];
        float* dst = (c < 64) ? g_zf : g_zb;
        int cd = (c < 64) ? c : c - 64;
#pragma unroll
        for (int mf = 0; mf < 4; mf++) {
            int m0 = base + wm + mf * 16 + g;
            if (m0 < NN)
                *reinterpret_cast<float2*>(&dst[(size_t)m0 * 64 + cd]) =
                    make_float2(acc[mf][nf][0] + bi0, acc[mf][nf][1] + bi1);
            int m1 = m0 + 8;
            if (m1 < NN)
                *reinterpret_cast<float2*>(&dst[(size_t)m1 * 64 + cd]) =
                    make_float2(acc[mf][nf][2] + bi0, acc[mf][nf][3] + bi1);
        }
    }
}

// ---------------- scatter: acc[t] += wf*zf[s]; acc[s] += wb*zb[t] ----------------
__device__ __forceinline__ void red4(float* p, float a, float b, float c, float d) {
    asm volatile("red.global.add.v4.f32 [%0], {%1, %2, %3, %4};"
                 :: "l"(p), "f"(a), "f"(b), "f"(c), "f"(d) : "memory");
}

__global__ __launch_bounds__(256) void k_scatter(const int* __restrict__ ei,
                                                 const float* __restrict__ ew) {
    unsigned tid = blockIdx.x * 256u + threadIdx.x;
    unsigned e = tid >> 4;               // 16 lanes per edge
    if (e >= NE) return;
    int sub = threadIdx.x & 15;

    int s = __ldg(&ei[e]);
    int t = __ldg(&ei[NE + e]);
    float w = __ldg(&ew[e]);
    if (s == t) w = 0.f;
    float df = __ldg(&g_degf[t]);
    float db = __ldg(&g_degb[s]);
    float wf = (df > 0.f) ? w / df : 0.f;
    float wb = (db > 0.f) ? w / db : 0.f;

    float4 vs = *reinterpret_cast<const float4*>(g_zf + (size_t)s * 64 + 4 * sub);
    red4(g_acc + (size_t)t * 64 + 4 * sub, wf * vs.x, wf * vs.y, wf * vs.z, wf * vs.w);
    float4 vt = *reinterpret_cast<const float4*>(g_zb + (size_t)t * 64 + 4 * sub);
    red4(g_acc + (size_t)s * 64 + 4 * sub, wb * vt.x, wb * vt.y, wb * vt.z, wb * vt.w);
}

// ---------------- fused GMM heads + outputs ----------------
#define JP 132
#define HEAD_SMEM ((3 * 32 * JP + 160 + 8 * 4 * 128) * 4)

__global__ __launch_bounds__(256) void k_head(const float* __restrict__ hh,
                                              const float* __restrict__ bf,
                                              const float* __restrict__ Wm,  const float* __restrict__ bm,
                                              const float* __restrict__ Wsg, const float* __restrict__ bsg,
                                              const float* __restrict__ Wp,  const float* __restrict__ bp,
                                              float* __restrict__ out, int write_extra) {
    extern __shared__ float sm[];
    float* Wmt = sm;                    // [32][JP]
    float* Wst = Wmt + 32 * JP;
    float* Wpt = Wst + 32 * JP;
    float* bfs = Wpt + 32 * JP;         // 64
    float* bms = bfs + 64;              // 32
    float* bss = bms + 32;              // 32
    float* bps = bss + 32;              // 32
    float* cat = bps + 32;              // [8 warps][4 nodes][128]

    for (int i = threadIdx.x; i < 32 * JP; i += 256) { Wmt[i] = 0.f; Wst[i] = 0.f; Wpt[i] = 0.f; }
    __syncthreads();
    for (int i = threadIdx.x; i < 128 * 32; i += 256) {
        int j = i >> 5, c = i & 31;
        Wmt[c * JP + j] = Wm[i];
        Wst[c * JP + j] = Wsg[i];
        Wpt[c * JP + j] = Wp[i];
    }
    if (threadIdx.x < 64) bfs[threadIdx.x] = bf[threadIdx.x];
    if (threadIdx.x < 32) {
        bms[threadIdx.x] = bm[threadIdx.x];
        bss[threadIdx.x] = bsg[threadIdx.x];
        bps[threadIdx.x] = bp[threadIdx.x];
    }
    __syncthreads();

    const int lane = threadIdx.x & 31;
    const int wrp  = threadIdx.x >> 5;
    float* mycat = cat + wrp * 4 * 128;

    float* ogmm = out;
    float* oo1  = out + (size_t)NN * 96;
    float* oh   = out + (size_t)NN * 96 + (size_t)NN * 128;

    int base = blockIdx.x * 32 + wrp * 4;          // 3125 * 32 = NN exactly

    float a0[4], a1[4], h0[4], h1[4];
#pragma unroll
    for (int s = 0; s < 4; s++) {
        size_t n = (size_t)(base + s);
        a0[s] = g_acc[n * 64 + lane]      + bfs[lane];
        a1[s] = g_acc[n * 64 + 32 + lane] + bfs[lane + 32];
        h0[s] = hh[n * 64 + lane];
        h1[s] = hh[n * 64 + 32 + lane];
        float* c = mycat + s * 128;
        c[lane]      = a0[s];
        c[lane + 32] = a1[s];
        c[lane + 64] = h0[s];
        c[lane + 96] = h1[s];
    }
    __syncwarp();

    float am[4] = {0.f, 0.f, 0.f, 0.f};
    float as_[4] = {0.f, 0.f, 0.f, 0.f};
    float ap[4] = {0.f, 0.f, 0.f, 0.f};
    {
        const float4* wmp = reinterpret_cast<const float4*>(Wmt + lane * JP);
        const float4* wsp = reinterpret_cast<const float4*>(Wst + lane * JP);
        const float4* wpp = reinterpret_cast<const float4*>(Wpt + lane * JP);
#pragma unroll 8
        for (int j4 = 0; j4 < 32; j4++) {
            float4 wm = wmp[j4], ws = wsp[j4], wq = wpp[j4];
#pragma unroll
            for (int s = 0; s < 4; s++) {
                float4 v = reinterpret_cast<const float4*>(mycat + s * 128)[j4];
                am[s]  += wm.x * v.x + wm.y * v.y + wm.z * v.z + wm.w * v.w;
                as_[s] += ws.x * v.x + ws.y * v.y + ws.z * v.z + ws.w * v.w;
                ap[s]  += wq.x * v.x + wq.y * v.y + wq.z * v.z + wq.w * v.w;
            }
        }
    }

#pragma unroll
    for (int s = 0; s < 4; s++) {
        size_t n = (size_t)(base + s);
        float mu = am[s] + bms[lane];
        float sg = as_[s] + bss[lane];
        sg = fmaxf(sg, 0.f) + log1pf(__expf(-fabsf(sg)));   // stable softplus
        float pv = ap[s] + bps[lane];
        float m = pv;
#pragma unroll
        for (int o = 16; o; o >>= 1) m = fmaxf(m, __shfl_xor_sync(0xFFFFFFFFu, m, o));
        float ex = __expf(pv - m);
        float ssum = ex;
#pragma unroll
        for (int o = 16; o; o >>= 1) ssum += __shfl_xor_sync(0xFFFFFFFFu, ssum, o);
        float pi = ex / ssum;

        ogmm[n * 96 + lane]      = mu;
        ogmm[n * 96 + 32 + lane] = sg;
        ogmm[n * 96 + 64 + lane] = pi;
        if (write_extra) {
            oo1[n * 128 + lane]      = a0[s];
            oo1[n * 128 + 32 + lane] = a1[s];
            oo1[n * 128 + 64 + lane] = h0[s];
            oo1[n * 128 + 96 + lane] = h1[s];
            oh[n * 64 + lane]      = h0[s];
            oh[n * 64 + 32 + lane] = h1[s];
        }
    }
}

// ---------------- launch ----------------
extern "C" void kernel_launch(void* const* d_in, const int* in_sizes, int n_in,
                              void* d_out, int out_size) {
    const float* x   = (const float*)d_in[0];
    const float* xh  = (const float*)d_in[1];
    const float* h   = (const float*)d_in[2];
    const int*   ei  = (const int*)d_in[3];
    const float* ew  = (const float*)d_in[4];
    const float* Win = (const float*)d_in[5];
    const float* bin = (const float*)d_in[6];
    const float* Wf  = (const float*)d_in[7];
    const float* bf  = (const float*)d_in[8];
    const float* Wm  = (const float*)d_in[9];
    const float* bm  = (const float*)d_in[10];
    const float* Wsg = (const float*)d_in[11];
    const float* bsg = (const float*)d_in[12];
    const float* Wp  = (const float*)d_in[13];
    const float* bp  = (const float*)d_in[14];
    float* out = (float*)d_out;

    int write_extra = (out_size >= NN * 96 + NN * 128 + NN * 64) ? 1 : 0;

    cudaFuncSetAttribute(k_z,    cudaFuncAttributeMaxDynamicSharedMemorySize, Z_SMEM);
    cudaFuncSetAttribute(k_head, cudaFuncAttributeMaxDynamicSharedMemorySize, HEAD_SMEM);

    k_init<<<148, 256>>>();
    k_wfold<<<128, 192>>>(Win, bin, Wf);
    k_deg<<<(NE + 255) / 256, 256>>>(ei, ew);
    k_z<<<(NN + 127) / 128, 256, Z_SMEM>>>(x, xh, h);
    k_scatter<<<(NE * 16) / 256, 256>>>(ei, ew);
    k_head<<<3125, 256, HEAD_SMEM>>>(h, bf, Wm, bm, Wsg, bsg, Wp, bp, out, write_extra);
}

// round 7
// speedup vs baseline: 1.6684x; 1.1705x over previous
#include <cuda_runtime.h>
#include <math.h>
#include <stdint.h>

#define NN 100000
#define NE 1600000
#define KTOT 168          // z-GEMM K padded 161 -> 168
#define KPAD 172          // z-GEMM A smem stride
#define KP2 132           // head A smem stride (conflict-free: 132 mod 32 = 4)
#define HD 100            // head result smem stride

// ---------------- scratch (device globals: allocation-free) ----------------
__device__ __align__(16) float g_zf[NN * 64];
__device__ __align__(16) float g_zb[NN * 64];
__device__ __align__(16) float g_acc[NN * 64];
__device__ float g_degf[NN];
__device__ float g_degb[NN];
__device__ __align__(16) float g_Wk[KTOT * 128]; // folded z weights (tf32), [k][c]
__device__ __align__(16) float g_bz[128];
__device__ __align__(16) float g_Wh[128 * 96];   // head weights [k][mu|sig|pi] (tf32)
__device__ __align__(16) int4  g_erec[NE];       // (s, t, bits(wf), bits(wb))

// ---------------- helpers ----------------
__device__ __forceinline__ unsigned f2tf32(float v) {
    unsigned o; asm("cvt.rna.tf32.f32 %0, %1;" : "=r"(o) : "f"(v)); return o;
}

__device__ __forceinline__ void mma_tf32(float* d,
                                         unsigned a0, unsigned a1, unsigned a2, unsigned a3,
                                         unsigned b0, unsigned b1) {
    asm volatile("mma.sync.aligned.m16n8k8.row.col.f32.tf32.tf32.f32 "
                 "{%0,%1,%2,%3}, {%4,%5,%6,%7}, {%8,%9}, {%0,%1,%2,%3};"
                 : "+f"(d[0]), "+f"(d[1]), "+f"(d[2]), "+f"(d[3])
                 : "r"(a0), "r"(a1), "r"(a2), "r"(a3), "r"(b0), "r"(b1));
}

// ---------------- init accumulator + degrees ----------------
__global__ void k_init() {
    int i = blockIdx.x * blockDim.x + threadIdx.x;
    int st = gridDim.x * blockDim.x;
    float4 z = make_float4(0.f, 0.f, 0.f, 0.f);
    for (int j = i; j < NN * 16; j += st)
        reinterpret_cast<float4*>(g_acc)[j] = z;
    for (int j = i; j < NN; j += st) { g_degf[j] = 0.f; g_degb[j] = 0.f; }
}

// ---------------- fold W_filt into W_in (k-major, tf32) ----------------
__global__ void k_wfold(const float* __restrict__ Win, const float* __restrict__ bin,
                        const float* __restrict__ Wf) {
    __shared__ float wsel[64];
    int c = blockIdx.x;                 // 0..127
    if (threadIdx.x < 64) {
        int j = threadIdx.x;
        wsel[j] = (c < 64) ? Wf[j * 64 + c] : Wf[(64 + j) * 64 + (c - 64)];
    }
    __syncthreads();
    int k = threadIdx.x;
    if (k < KTOT) {
        float a = 0.f;
        if (k < 161) {
#pragma unroll 8
            for (int j = 0; j < 64; j++) a += Win[k * 64 + j] * wsel[j];
        }
        g_Wk[k * 128 + c] = __uint_as_float(f2tf32(a));
    }
    if (threadIdx.x == 0) {
        float b = 0.f;
        for (int j = 0; j < 64; j++) b += bin[j] * wsel[j];
        g_bz[c] = b;
    }
}

// ---------------- pack head weights [Wm|Ws|Wp] -> g_Wh[k][96] (tf32) ----------------
__global__ void k_whead(const float* __restrict__ Wm, const float* __restrict__ Wsg,
                        const float* __restrict__ Wp) {
    int c = blockIdx.x;                 // 0..95
    int j = threadIdx.x;                // 0..127
    float v = (c < 32) ? Wm[j * 32 + c]
            : (c < 64) ? Wsg[j * 32 + (c - 32)]
                       : Wp[j * 32 + (c - 64)];
    g_Wh[j * 96 + c] = __uint_as_float(f2tf32(v));
}

// ---------------- weighted degrees ----------------
__global__ void k_deg(const int* __restrict__ ei, const float* __restrict__ ew) {
    int e = blockIdx.x * blockDim.x + threadIdx.x;
    if (e >= NE) return;
    int s = ei[e], t = ei[NE + e];
    float w = ew[e];
    if (s != t) {
        atomicAdd(&g_degf[t], w);
        atomicAdd(&g_degb[s], w);
    }
}

// ---------------- per-edge record ----------------
__global__ void k_prep(const int* __restrict__ ei, const float* __restrict__ ew) {
    int e = blockIdx.x * blockDim.x + threadIdx.x;
    if (e >= NE) return;
    int s = ei[e], t = ei[NE + e];
    float w = (s == t) ? 0.f : ew[e];
    float df = __ldg(&g_degf[t]);
    float db = __ldg(&g_degb[s]);
    float wf = (df > 0.f) ? w / df : 0.f;
    float wb = (db > 0.f) ? w / db : 0.f;
    g_erec[e] = make_int4(s, t, __float_as_int(wf), __float_as_int(wb));
}

// ---------------- z = A @ Wc + bz  (tf32 MMA) ----------------
#define Z_SMEM (128 * KPAD * 4)

__global__ __launch_bounds__(256) void k_z(const float* __restrict__ x,
                                           const float* __restrict__ xh,
                                           const float* __restrict__ hh) {
    extern __shared__ float As[];       // [128][KPAD]
    const int tid = threadIdx.x;
    const int base = blockIdx.x * 128;

    for (int i = tid; i < 128 * KPAD / 4; i += 256)
        reinterpret_cast<float4*>(As)[i] = make_float4(0.f, 0.f, 0.f, 0.f);
    __syncthreads();

    {
        int lim = min(128, NN - base);
        if (tid < lim) As[tid * KPAD] = __uint_as_float(f2tf32(x[base + tid]));
        for (int i = tid; i < lim * 96; i += 256) {
            int m = i / 96, k = i - m * 96;
            As[m * KPAD + 1 + k] = __uint_as_float(f2tf32(xh[(size_t)(base + m) * 96 + k]));
        }
        for (int i = tid; i < lim * 64; i += 256) {
            int m = i >> 6, k = i & 63;
            As[m * KPAD + 97 + k] = __uint_as_float(f2tf32(hh[(size_t)(base + m) * 64 + k]));
        }
    }
    __syncthreads();

    const int lane = tid & 31;
    const int w    = tid >> 5;
    const int wm = (w >> 2) * 64;
    const int wn = (w & 3) * 32;
    const int g = lane >> 2, t = lane & 3;
    const unsigned* Au = reinterpret_cast<const unsigned*>(As);

    float acc[4][4][4];
#pragma unroll
    for (int mf = 0; mf < 4; mf++)
#pragma unroll
        for (int nf = 0; nf < 4; nf++)
#pragma unroll
            for (int q = 0; q < 4; q++) acc[mf][nf][q] = 0.f;

#pragma unroll 1
    for (int ks = 0; ks < 21; ks++) {
        const int k0 = ks * 8;
        unsigned bfr[4][2];
#pragma unroll
        for (int nf = 0; nf < 4; nf++) {
            int nc = wn + nf * 8 + g;
            bfr[nf][0] = __float_as_uint(__ldg(&g_Wk[(k0 + t) * 128 + nc]));
            bfr[nf][1] = __float_as_uint(__ldg(&g_Wk[(k0 + 4 + t) * 128 + nc]));
        }
#pragma unroll
        for (int mf = 0; mf < 4; mf++) {
            int r0 = wm + mf * 16 + g;
            unsigned a0 = Au[r0 * KPAD + k0 + t];
            unsigned a1 = Au[(r0 + 8) * KPAD + k0 + t];
            unsigned a2 = Au[r0 * KPAD + k0 + 4 + t];
            unsigned a3 = Au[(r0 + 8) * KPAD + k0 + 4 + t];
#pragma unroll
            for (int nf = 0; nf < 4; nf++)
                mma_tf32(acc[mf][nf], a0, a1, a2, a3, bfr[nf][0], bfr[nf][1]);
        }
    }

#pragma unroll
    for (int nf = 0; nf < 4; nf++) {
        int c = wn + nf * 8 + 2 * t;
        float bi0 = g_bz[c], bi1 = g_bz[c + 1];
        float* dst = (c < 64) ? g_zf : g_zb;
        int cd = (c < 64) ? c : c - 64;
#pragma unroll
        for (int mf = 0; mf < 4; mf++) {
            int m0 = base + wm + mf * 16 + g;
            if (m0 < NN)
                *reinterpret_cast<float2*>(&dst[(size_t)m0 * 64 + cd]) =
                    make_float2(acc[mf][nf][0] + bi0, acc[mf][nf][1] + bi1);
            int m1 = m0 + 8;
            if (m1 < NN)
                *reinterpret_cast<float2*>(&dst[(size_t)m1 * 64 + cd]) =
                    make_float2(acc[mf][nf][2] + bi0, acc[mf][nf][3] + bi1);
        }
    }
}

// ---------------- scatter (record-based) ----------------
__device__ __forceinline__ void red4(float* p, float a, float b, float c, float d) {
    asm volatile("red.global.add.v4.f32 [%0], {%1, %2, %3, %4};"
                 :: "l"(p), "f"(a), "f"(b), "f"(c), "f"(d) : "memory");
}

__global__ __launch_bounds__(256) void k_scatter() {
    unsigned tid = blockIdx.x * 256u + threadIdx.x;
    unsigned e = tid >> 4;               // 16 lanes per edge
    if (e >= NE) return;
    int sub = threadIdx.x & 15;

    int4 rec = __ldg(&g_erec[e]);
    int s = rec.x, t = rec.y;
    float wf = __int_as_float(rec.z);
    float wb = __int_as_float(rec.w);

    float4 vs = *reinterpret_cast<const float4*>(g_zf + (size_t)s * 64 + 4 * sub);
    red4(g_acc + (size_t)t * 64 + 4 * sub, wf * vs.x, wf * vs.y, wf * vs.z, wf * vs.w);
    float4 vt = *reinterpret_cast<const float4*>(g_zb + (size_t)t * 64 + 4 * sub);
    red4(g_acc + (size_t)s * 64 + 4 * sub, wb * vt.x, wb * vt.y, wb * vt.z, wb * vt.w);
}

// ---------------- head: tf32 MMA GMM heads + outputs ----------------
#define HEAD_SMEM (128 * KP2 * 4)

__global__ __launch_bounds__(256) void k_head(const float* __restrict__ hh,
                                              const float* __restrict__ bf,
                                              const float* __restrict__ bm,
                                              const float* __restrict__ bsg,
                                              const float* __restrict__ bp,
                                              float* __restrict__ out, int write_extra) {
    extern __shared__ float sms[];
    float* As = sms;                     // [128][KP2], later aliased as hd [128][HD]
    float* hd = sms;

    const int tid = threadIdx.x;
    const int base = blockIdx.x * 128;
    const int lim = min(128, NN - base);

    float* ogmm = out;
    float* oo1  = out + (size_t)NN * 96;
    float* oh   = out + (size_t)NN * 96 + (size_t)NN * 128;

    // zero-fill A (covers m >= lim and pad)
    for (int i = tid; i < 128 * KP2 / 4; i += 256)
        reinterpret_cast<float4*>(As)[i] = make_float4(0.f, 0.f, 0.f, 0.f);
    __syncthreads();

    // stage out1 = [acc + bf | h]; write oo1/oh in fp32 on the way
    for (int i = tid; i < lim * 64; i += 256) {
        int m = i >> 6, k = i & 63;
        size_t n = (size_t)(base + m);
        float a = g_acc[n * 64 + k] + __ldg(&bf[k]);
        float hv = hh[n * 64 + k];
        As[m * KP2 + k]      = __uint_as_float(f2tf32(a));
        As[m * KP2 + 64 + k] = __uint_as_float(f2tf32(hv));
        if (write_extra) {
            oo1[n * 128 + k]      = a;
            oo1[n * 128 + 64 + k] = hv;
            oh[n * 64 + k]        = hv;
        }
    }
    __syncthreads();

    const int lane = tid & 31;
    const int w    = tid >> 5;
    const int wm = (w >> 2) * 64;        // 0 | 64
    const int wn = (w & 3) * 24;         // 0,24,48,72  (total N = 96)
    const int g = lane >> 2, t = lane & 3;
    const unsigned* Au = reinterpret_cast<const unsigned*>(As);

    float acc[4][3][4];
#pragma unroll
    for (int mf = 0; mf < 4; mf++)
#pragma unroll
        for (int nf = 0; nf < 3; nf++)
#pragma unroll
            for (int q = 0; q < 4; q++) acc[mf][nf][q] = 0.f;

#pragma unroll 1
    for (int ks = 0; ks < 16; ks++) {
        const int k0 = ks * 8;
        unsigned bfr[3][2];
#pragma unroll
        for (int nf = 0; nf < 3; nf++) {
            int nc = wn + nf * 8 + g;
            bfr[nf][0] = __float_as_uint(__ldg(&g_Wh[(k0 + t) * 96 + nc]));
            bfr[nf][1] = __float_as_uint(__ldg(&g_Wh[(k0 + 4 + t) * 96 + nc]));
        }
#pragma unroll
        for (int mf = 0; mf < 4; mf++) {
            int r0 = wm + mf * 16 + g;
            unsigned a0 = Au[r0 * KP2 + k0 + t];
            unsigned a1 = Au[(r0 + 8) * KP2 + k0 + t];
            unsigned a2 = Au[r0 * KP2 + k0 + 4 + t];
            unsigned a3 = Au[(r0 + 8) * KP2 + k0 + 4 + t];
#pragma unroll
            for (int nf = 0; nf < 3; nf++)
                mma_tf32(acc[mf][nf], a0, a1, a2, a3, bfr[nf][0], bfr[nf][1]);
        }
    }
    __syncthreads();   // all warps done reading As; safe to overwrite as hd

    // dump MMA results to smem hd[row][96]
#pragma unroll
    for (int nf = 0; nf < 3; nf++) {
        int c = wn + nf * 8 + 2 * t;
#pragma unroll
        for (int mf = 0; mf < 4; mf++) {
            int r0 = wm + mf * 16 + g;
            *reinterpret_cast<float2*>(&hd[r0 * HD + c]) =
                make_float2(acc[mf][nf][0], acc[mf][nf][1]);
            *reinterpret_cast<float2*>(&hd[(r0 + 8) * HD + c]) =
                make_float2(acc[mf][nf][2], acc[mf][nf][3]);
        }
    }
    __syncthreads();

    // epilogue: warp w handles rows w*16 .. w*16+15
    const float bmv = __ldg(&bm[lane]);
    const float bsv = __ldg(&bsg[lane]);
    const float bpv = __ldg(&bp[lane]);
    for (int s = 0; s < 16; s++) {
        int row = w * 16 + s;
        int n = base + row;
        if (n >= NN) break;
        float mu = hd[row * HD + lane]      + bmv;
        float sg = hd[row * HD + 32 + lane] + bsv;
        sg = fmaxf(sg, 0.f) + log1pf(__expf(-fabsf(sg)));   // stable softplus
        float pv = hd[row * HD + 64 + lane] + bpv;
        float m = pv;
#pragma unroll
        for (int o = 16; o; o >>= 1) m = fmaxf(m, __shfl_xor_sync(0xFFFFFFFFu, m, o));
        float ex = __expf(pv - m);
        float ssum = ex;
#pragma unroll
        for (int o = 16; o; o >>= 1) ssum += __shfl_xor_sync(0xFFFFFFFFu, ssum, o);
        float pi = ex / ssum;

        ogmm[(size_t)n * 96 + lane]      = mu;
        ogmm[(size_t)n * 96 + 32 + lane] = sg;
        ogmm[(size_t)n * 96 + 64 + lane] = pi;
    }
}

// ---------------- launch ----------------
extern "C" void kernel_launch(void* const* d_in, const int* in_sizes, int n_in,
                              void* d_out, int out_size) {
    const float* x   = (const float*)d_in[0];
    const float* xh  = (const float*)d_in[1];
    const float* h   = (const float*)d_in[2];
    const int*   ei  = (const int*)d_in[3];
    const float* ew  = (const float*)d_in[4];
    const float* Win = (const float*)d_in[5];
    const float* bin = (const float*)d_in[6];
    const float* Wf  = (const float*)d_in[7];
    const float* bf  = (const float*)d_in[8];
    const float* Wm  = (const float*)d_in[9];
    const float* bm  = (const float*)d_in[10];
    const float* Wsg = (const float*)d_in[11];
    const float* bsg = (const float*)d_in[12];
    const float* Wp  = (const float*)d_in[13];
    const float* bp  = (const float*)d_in[14];
    float* out = (float*)d_out;

    int write_extra = (out_size >= NN * 96 + NN * 128 + NN * 64) ? 1 : 0;

    cudaFuncSetAttribute(k_z,    cudaFuncAttributeMaxDynamicSharedMemorySize, Z_SMEM);
    cudaFuncSetAttribute(k_head, cudaFuncAttributeMaxDynamicSharedMemorySize, HEAD_SMEM);

    k_init<<<148, 256>>>();
    k_wfold<<<128, 192>>>(Win, bin, Wf);
    k_whead<<<96, 128>>>(Wm, Wsg, Wp);
    k_deg<<<(NE + 255) / 256, 256>>>(ei, ew);
    k_prep<<<(NE + 255) / 256, 256>>>(ei, ew);
    k_z<<<(NN + 127) / 128, 256, Z_SMEM>>>(x, xh, h);
    k_scatter<<<(NE * 16) / 256, 256>>>();
    k_head<<<(NN + 127) / 128, 256, HEAD_SMEM>>>(h, bf, bm, bsg, bp, out, write_extra);
}